// round 4
// baseline (speedup 1.0000x reference)
#include <cuda_runtime.h>
#include <cstdint>

// FP8 E4M3 multiplier over "bit-vector" encoded tensors.
// Each fp8 value is 8 float32 bits [s, e3, e2, e1, e0, m2, m1, m0],
// each "bit" float exactly 0.0f (0x00000000) or 1.0f (0x3f800000).
// Integer-domain bit extraction: bit = (raw >> 29) & 1
//   (0x3f800000 has bit 29 set; 0 does not).
// Output bit word = (-bit) & 0x3f800000.

__device__ __forceinline__ unsigned bw(int bit) {      // bit(0/1) -> 0.0f/1.0f raw
    return (unsigned)(-bit) & 0x3f800000u;
}

__device__ __forceinline__ void fp8mul_core(
    uint4 alo, uint4 ahi, uint4 blo, uint4 bhi,
    uint4& olo, uint4& ohi)
{
    // decode: bit = (w >> 29) & 1
    int sa =  (alo.x >> 29) & 1;
    int ea = (((alo.y >> 29) & 1) << 3) | (((alo.z >> 29) & 1) << 2)
           | (((alo.w >> 29) & 1) << 1) |  ((ahi.x >> 29) & 1);
    int ma = (((ahi.y >> 29) & 1) << 2) | (((ahi.z >> 29) & 1) << 1)
           |  ((ahi.w >> 29) & 1);
    int sb =  (blo.x >> 29) & 1;
    int eb = (((blo.y >> 29) & 1) << 3) | (((blo.z >> 29) & 1) << 2)
           | (((blo.w >> 29) & 1) << 1) |  ((bhi.x >> 29) & 1);
    int mb = (((bhi.y >> 29) & 1) << 2) | (((bhi.z >> 29) & 1) << 1)
           |  ((bhi.w >> 29) & 1);

    int sig_a = (ea == 0) ? ma : (ma + 8);
    int sig_b = (eb == 0) ? mb : (mb + 8);
    int exa = ((ea == 0) ? 1 : ea) - 7;
    int exb = ((eb == 0) ? 1 : eb) - 7;

    int M = sig_a * sig_b;          // exact product, <= 225
    int E = exa + exb - 6;          // value = M * 2^E

    int p = (M > 0) ? (31 - __clz(M)) : 0;   // MSB position of M
    int eb_out = E + p + 7;

    // ---- normal path: RNE round to 3 mantissa bits ----
    int sh = p - 3;
    int mant4;
    if (sh > 0) {
        int q = M >> sh;
        int rem = M - (q << sh);
        int half = 1 << (sh - 1);
        mant4 = q + ((rem > half) | ((rem == half) & (q & 1)));
    } else {
        mant4 = M << (-sh);
    }
    int carry = mant4 >> 4;                 // rounding overflow
    if (mant4 == 16) mant4 = 8;
    int e_n = eb_out + carry;
    int m_n = mant4 - 8;
    if (e_n >= 16) { e_n = 15; m_n = 7; }   // overflow -> NaN pattern

    // ---- subnormal path (eb_out <= 0): mant = RNE(M * 2^(E+9)) ----
    int t = E + 9;
    int mant_s;
    if (t >= 0) {
        mant_s = M << t;
    } else {
        int shs = (-t < 30) ? -t : 30;
        int q = M >> shs;
        int rem = M - (q << shs);
        int half = 1 << (shs - 1);
        mant_s = q + ((rem > half) | ((rem == half) & (q & 1)));
    }
    int e_s = (mant_s >= 8) ? 1 : 0;
    int m_s = (mant_s >= 8) ? 0 : mant_s;

    // ---- select ----
    bool is_sub = (eb_out <= 0);
    int e_o = is_sub ? e_s : e_n;
    int m_o = is_sub ? m_s : m_n;
    if (M == 0) { e_o = 0; m_o = 0; }
    int s_o = sa ^ sb;

    olo.x = bw(s_o);
    olo.y = bw((e_o >> 3) & 1);
    olo.z = bw((e_o >> 2) & 1);
    olo.w = bw((e_o >> 1) & 1);
    ohi.x = bw(e_o & 1);
    ohi.y = bw((m_o >> 2) & 1);
    ohi.z = bw((m_o >> 1) & 1);
    ohi.w = bw(m_o & 1);
}

// 2 elements per thread; all loads front-batched for MLP; streaming hints.
__global__ void __launch_bounds__(256) fp8mul_kernel(
    const uint4* __restrict__ a4,
    const uint4* __restrict__ b4,
    uint4* __restrict__ o4,
    int n)
{
    int base = blockIdx.x * (2 * 256) + threadIdx.x;   // element index of item 0
    int i0 = base;
    int i1 = base + 256;

    if (i1 < n) {
        // front-batch all 8 loads (MLP = 8)
        uint4 a0lo = __ldcs(&a4[2 * i0]);
        uint4 a0hi = __ldcs(&a4[2 * i0 + 1]);
        uint4 b0lo = __ldcs(&b4[2 * i0]);
        uint4 b0hi = __ldcs(&b4[2 * i0 + 1]);
        uint4 a1lo = __ldcs(&a4[2 * i1]);
        uint4 a1hi = __ldcs(&a4[2 * i1 + 1]);
        uint4 b1lo = __ldcs(&b4[2 * i1]);
        uint4 b1hi = __ldcs(&b4[2 * i1 + 1]);

        uint4 o0lo, o0hi, o1lo, o1hi;
        fp8mul_core(a0lo, a0hi, b0lo, b0hi, o0lo, o0hi);
        fp8mul_core(a1lo, a1hi, b1lo, b1hi, o1lo, o1hi);

        __stcs(&o4[2 * i0],     o0lo);
        __stcs(&o4[2 * i0 + 1], o0hi);
        __stcs(&o4[2 * i1],     o1lo);
        __stcs(&o4[2 * i1 + 1], o1hi);
    } else {
        // tail (not hit with n = 1024*4096 and this grid, but keep it correct)
        for (int i = i0; i < n; i += 256) {
            uint4 alo = __ldcs(&a4[2 * i]);
            uint4 ahi = __ldcs(&a4[2 * i + 1]);
            uint4 blo = __ldcs(&b4[2 * i]);
            uint4 bhi = __ldcs(&b4[2 * i + 1]);
            uint4 olo, ohi;
            fp8mul_core(alo, ahi, blo, bhi, olo, ohi);
            __stcs(&o4[2 * i],     olo);
            __stcs(&o4[2 * i + 1], ohi);
        }
    }
}

extern "C" void kernel_launch(void* const* d_in, const int* in_sizes, int n_in,
                              void* d_out, int out_size)
{
    const uint4* a = (const uint4*)d_in[0];
    const uint4* b = (const uint4*)d_in[1];
    uint4* o = (uint4*)d_out;
    int n = in_sizes[0] / 8;                 // fp8 element count
    int threads = 256;
    int elems_per_block = 2 * threads;
    int blocks = (n + elems_per_block - 1) / elems_per_block;
    fp8mul_kernel<<<blocks, threads>>>(a, b, o, n);
}